// round 11
// baseline (speedup 1.0000x reference)
#include <cuda_runtime.h>
#include <cstdint>

// Involution2d on GB300 (sm_103 base ISA). B=4, C=256, H=W=64, G=16, K=7, PAD=3.
// R11 = R9 fused kernel + fast w-pack + triple-buffered mainloop (1 barrier/chunk).
// Block = (b, h-pair, gq-pair): 256 threads, 2 rows, 2 groups, 2 blocks/SM.

#define CH 256
#define HH 64
#define WW 64
#define KT 7
#define KK 49
#define CC 32                  // channels per chunk
#define NCHUNK 8
#define TAPS 112               // 2 groups * 56 padded taps
#define PX 128                 // pixels per block (2 rows)
#define KROW 132               // k_s row stride, 132%32=4 -> conflict-free

#define XBUF_F (CC * PX)       // 4096 floats
#define WBUF_F (CC * TAPS)     // 3584 floats
#define SMEM_BYTES (3 * (XBUF_F + WBUF_F) * 4)   // 92160 B; k_s alias needs 51744 B

// g_wt2: [cgOctet 32][gqp 8][n 112][8], 8 = (unit<<1)|half with
//   unit = (k8 & 3) ^ ((n >> 2) & 3), half = k8 >> 2, k8 = channel & 7
__device__ float g_wt2[32 * 8 * TAPS * 8];

// ---------------- helpers ----------------
__device__ __forceinline__ uint32_t f2tf32u(float x) {
    uint32_t u;
    asm("cvt.rn.tf32.f32 %0, %1;" : "=r"(u) : "f"(x));
    return u;
}
__device__ __forceinline__ void cp16(float* dst, const float* src) {
    unsigned sa = (unsigned)__cvta_generic_to_shared(dst);
    asm volatile("cp.async.cg.shared.global [%0], [%1], 16;" :: "r"(sa), "l"(src));
}
__device__ __forceinline__ void cp_commit() { asm volatile("cp.async.commit_group;"); }
__device__ __forceinline__ void cp_wait1()  { asm volatile("cp.async.wait_group 1;"); }
__device__ __forceinline__ void cp_wait0()  { asm volatile("cp.async.wait_group 0;"); }

__device__ __forceinline__ void mma8(float* c, const uint32_t* a, const uint32_t* b) {
    asm volatile(
        "mma.sync.aligned.m16n8k8.row.col.f32.tf32.tf32.f32 "
        "{%0,%1,%2,%3}, {%4,%5,%6,%7}, {%8,%9}, {%0,%1,%2,%3};"
        : "+f"(c[0]), "+f"(c[1]), "+f"(c[2]), "+f"(c[3])
        : "r"(a[0]), "r"(a[1]), "r"(a[2]), "r"(a[3]), "r"(b[0]), "r"(b[1]));
}

// ---------------- fast w repack: 1 thread per (blk, n) ----------------
// grid 112 x 256 threads; thread u -> blk = u/112, n = u%112.
// Reads 8 consecutive channels (2 LDG.128), permutes in regs, 2 STG.128.
__global__ __launch_bounds__(256)
void wt_pack_kernel(const float* __restrict__ wk) {
    const int u = blockIdx.x * 256 + threadIdx.x;   // 0..28671
    const int blk = u / 112;
    const int n = u - blk * 112;
    const int cgO = blk >> 3, gqp = blk & 7;
    const int grp = n / 56, kk = n - grp * 56;
    const int c0 = cgO * 8;
    float* dst = g_wt2 + (size_t)u * 8;

    float o[8];
    if (kk < KK) {
        const float* src = wk + (size_t)((gqp * 2 + grp) * KK + kk) * CH + c0;
        const float4 s0 = *(const float4*)(src);
        const float4 s1 = *(const float4*)(src + 4);
        const float s[8] = {s0.x, s0.y, s0.z, s0.w, s1.x, s1.y, s1.z, s1.w};
        const int xorv = (n >> 2) & 3;
        #pragma unroll
        for (int k8 = 0; k8 < 8; ++k8) {
            const int unit = (k8 & 3) ^ xorv;
            const int half = k8 >> 2;
            o[unit * 2 + half] = __uint_as_float(f2tf32u(s[k8]));
        }
    } else {
        #pragma unroll
        for (int i = 0; i < 8; ++i) o[i] = 0.0f;
    }
    *(float4*)(dst)     = make_float4(o[0], o[1], o[2], o[3]);
    *(float4*)(dst + 4) = make_float4(o[4], o[5], o[6], o[7]);
}

// ---------------- fused main kernel ----------------
__global__ __launch_bounds__(256, 2)
void invo_main_kernel(const float* __restrict__ x,
                      const float* __restrict__ bk,
                      float* __restrict__ out) {
    extern __shared__ float sm[];
    float* k_s = sm;                        // [slot 98][KROW], aliased after stage 1

    const int t   = threadIdx.x;
    const int rb  = blockIdx.x;
    const int b   = rb >> 5;
    const int h   = (rb & 31) * 2;          // rows h, h+1
    const int gqp = blockIdx.y;             // group pair 0..7

    auto xbuf = [&](int i) { return sm + i * XBUF_F; };
    auto wbuf = [&](int i) { return sm + 3 * XBUF_F + i * WBUF_F; };

    // ---- chunk loader ----
    auto load_chunk = [&](int chunk, int bi) {
        const int c0 = chunk * CC;
        float* xb = xbuf(bi);
        float* wb = wbuf(bi);
        #pragma unroll
        for (int i = 0; i < 4; ++i) {                 // 1024 cp16
            const int u = t + 256 * i;
            const int k = u >> 5;
            const int p4 = (u & 31) << 2;
            cp16(xb + k * PX + (p4 ^ (8 * (k & 3))),
                 x + ((size_t)(b * CH + c0 + k)) * 4096 + h * 64 + p4);
        }
        #pragma unroll
        for (int i = 0; i < 4; ++i) {                 // 896 cp16
            const int u = t + 256 * i;
            if (u < 896) {
                const int cg = u / 224;               // channel octet within chunk
                const int r = u - cg * 224;           // float4 unit within slab
                cp16(wb + cg * (TAPS * 8) + r * 4,
                     g_wt2 + ((size_t)((chunk * 4 + cg) * 8 + gqp) * TAPS) * 8 + r * 4);
            }
        }
        cp_commit();
    };

    // ---- Stage 1: mma.sync tf32, 8 warps, warp tile m32 x n56 ----
    const int wid = t >> 5, lane = t & 31;
    const int la = lane & 3, gid = lane >> 2;
    const int mq = wid & 3, nq = wid >> 2;  // nq 0..1
    const int m0w = mq * 32;
    const int n0w = nq * 56;
    const int sw = 8 * la;

    float acc[2][7][4];
    #pragma unroll
    for (int mt = 0; mt < 2; ++mt)
        #pragma unroll
        for (int nt = 0; nt < 7; ++nt)
            #pragma unroll
            for (int i = 0; i < 4; ++i) acc[mt][nt][i] = 0.0f;

    load_chunk(0, 0);
    load_chunk(1, 1);

    for (int ch = 0; ch < NCHUNK; ++ch) {
        if (ch < NCHUNK - 1) cp_wait1(); else cp_wait0();
        __syncthreads();                   // chunk ch data visible; MMA(ch-1) done by all
        if (ch + 2 < NCHUNK) load_chunk(ch + 2, (ch + 2) % 3);

        const float* xb = xbuf(ch % 3);
        const float* wb = wbuf(ch % 3);

        #pragma unroll
        for (int ks = 0; ks < 4; ++ks) {
            const int kb = ks * 8;
            uint32_t af[2][4];
            #pragma unroll
            for (int mt = 0; mt < 2; ++mt) {
                const int rm = m0w + mt * 16;
                const int r0 = (rm + gid) ^ sw;
                const int r1 = (rm + 8 + gid) ^ sw;
                af[mt][0] = f2tf32u(xb[(kb + la) * PX + r0]);
                af[mt][1] = f2tf32u(xb[(kb + la) * PX + r1]);
                af[mt][2] = f2tf32u(xb[(kb + la + 4) * PX + r0]);
                af[mt][3] = f2tf32u(xb[(kb + la + 4) * PX + r1]);
            }
            const float* wrow = wb + ks * (TAPS * 8);
            #pragma unroll
            for (int nt = 0; nt < 7; ++nt) {
                const int cn = n0w + nt * 8 + gid;
                const int unit = la ^ ((cn >> 2) & 3);
                const float2 bv = *(const float2*)(wrow + cn * 8 + unit * 2);
                uint32_t bf[2] = {__float_as_uint(bv.x), __float_as_uint(bv.y)};
                mma8(acc[0][nt], af[0], bf);
                mma8(acc[1][nt], af[1], bf);
            }
        }
    }
    __syncthreads();                       // all MMA smem reads done before k_s alias

    // ---- epilogue: bias add, write k_s[slot = nq*49+kk][px] ----
    {
        const int px0 = m0w + gid;
        #pragma unroll
        for (int nt = 0; nt < 7; ++nt) {
            const int kk = nt * 8 + la * 2;
            if (kk < KK) {
                const float bias = bk[(gqp * 2 + nq) * KK + kk];
                const int s = nq * KK + kk;
                k_s[s * KROW + px0]      = acc[0][nt][0] + bias;
                k_s[s * KROW + px0 + 8]  = acc[0][nt][2] + bias;
                k_s[s * KROW + px0 + 16] = acc[1][nt][0] + bias;
                k_s[s * KROW + px0 + 24] = acc[1][nt][2] + bias;
            }
            if (kk + 1 < KK) {
                const float bias1 = bk[(gqp * 2 + nq) * KK + kk + 1];
                const int s1 = nq * KK + kk + 1;
                k_s[s1 * KROW + px0]      = acc[0][nt][1] + bias1;
                k_s[s1 * KROW + px0 + 8]  = acc[0][nt][3] + bias1;
                k_s[s1 * KROW + px0 + 16] = acc[1][nt][1] + bias1;
                k_s[s1 * KROW + px0 + 24] = acc[1][nt][3] + bias1;
            }
        }
    }
    __syncthreads();

    // ---- Stage 2: apply per-pixel 7x7 kernels (fp32) ----
    const int pxg  = t & 15, w0 = pxg << 2;
    const int chq  = (t >> 4) & 3;
    const int grp2 = (t >> 6) & 1;
    const int hrow = t >> 7;
    const int hout = h + hrow;

    float o[4][4];
    #pragma unroll
    for (int m = 0; m < 4; ++m)
        #pragma unroll
        for (int pi = 0; pi < 4; ++pi) o[m][pi] = 0.0f;

    #pragma unroll
    for (int kh = 0; kh < KT; ++kh) {
        const int hh = hout + kh - 3;
        if ((unsigned)hh >= (unsigned)HH) continue;

        float4 kvf[KT];
        #pragma unroll
        for (int kw = 0; kw < KT; ++kw)
            kvf[kw] = *(const float4*)&k_s[(grp2 * KK + kh * KT + kw) * KROW + hrow * 64 + w0];

        #pragma unroll
        for (int m = 0; m < 4; ++m) {
            const int c = gqp * 32 + grp2 * 16 + chq + (m << 2);
            const float* xr = x + ((size_t)(b * CH + c) * HH + hh) * WW;
            const float4 A = (pxg >= 1)  ? *(const float4*)(xr + w0 - 4)
                                         : make_float4(0.f, 0.f, 0.f, 0.f);
            const float4 Bv = *(const float4*)(xr + w0);
            const float4 Cc = (pxg <= 14) ? *(const float4*)(xr + w0 + 4)
                                          : make_float4(0.f, 0.f, 0.f, 0.f);
            const float xv[10] = {A.y, A.z, A.w, Bv.x, Bv.y, Bv.z, Bv.w, Cc.x, Cc.y, Cc.z};
            #pragma unroll
            for (int kw = 0; kw < KT; ++kw) {
                o[m][0] += xv[kw]     * kvf[kw].x;
                o[m][1] += xv[kw + 1] * kvf[kw].y;
                o[m][2] += xv[kw + 2] * kvf[kw].z;
                o[m][3] += xv[kw + 3] * kvf[kw].w;
            }
        }
    }

    #pragma unroll
    for (int m = 0; m < 4; ++m) {
        const int c = gqp * 32 + grp2 * 16 + chq + (m << 2);
        *reinterpret_cast<float4*>(out + ((size_t)(b * CH + c) * HH + hout) * WW + w0) =
            make_float4(o[m][0], o[m][1], o[m][2], o[m][3]);
    }
}

extern "C" void kernel_launch(void* const* d_in, const int* in_sizes, int n_in,
                              void* d_out, int out_size) {
    const float* x  = (const float*)d_in[0];
    const float* wk = (const float*)d_in[1];
    const float* bk = (const float*)d_in[2];
    float* out      = (float*)d_out;

    wt_pack_kernel<<<112, 256>>>(wk);

    cudaFuncSetAttribute(invo_main_kernel,
                         cudaFuncAttributeMaxDynamicSharedMemorySize, SMEM_BYTES);
    dim3 grid(4 * 32, 8);               // (b*hpair, gq-pair) = (128, 8) = 1024 blocks
    invo_main_kernel<<<grid, 256, SMEM_BYTES>>>(x, bk, out);
}

// round 12
// speedup vs baseline: 1.5143x; 1.5143x over previous
#include <cuda_runtime.h>
#include <cstdint>

// Involution2d on GB300 (sm_103 base ISA). B=4, C=256, H=W=64, G=16, K=7, PAD=3.
// R12 = R9 fused main kernel (double-buffered, 60KB smem) + fast w-pack.
// Block = (b, h-pair, gq-pair): 256 threads, 2 rows, 2 groups, 2 blocks/SM.

#define CH 256
#define HH 64
#define WW 64
#define KT 7
#define KK 49
#define CC 32                  // channels per chunk
#define NCHUNK 8
#define TAPS 112               // 2 groups * 56 padded taps
#define PX 128                 // pixels per block (2 rows)
#define KROW 132               // k_s row stride, 132%32=4 -> conflict-free

#define XBUF_F (CC * PX)       // 4096 floats
#define WBUF_F (CC * TAPS)     // 3584 floats
#define SMEM_BYTES ((2 * XBUF_F + 2 * WBUF_F) * 4)   // 61440 B; k_s alias 51744 B

// g_wt2: [cgOctet 32][gqp 8][n 112][8], 8 = (unit<<1)|half with
//   unit = (k8 & 3) ^ ((n >> 2) & 3), half = k8 >> 2, k8 = channel & 7
__device__ float g_wt2[32 * 8 * TAPS * 8];

// ---------------- helpers ----------------
__device__ __forceinline__ uint32_t f2tf32u(float x) {
    uint32_t u;
    asm("cvt.rn.tf32.f32 %0, %1;" : "=r"(u) : "f"(x));
    return u;
}
__device__ __forceinline__ void cp16(float* dst, const float* src) {
    unsigned sa = (unsigned)__cvta_generic_to_shared(dst);
    asm volatile("cp.async.cg.shared.global [%0], [%1], 16;" :: "r"(sa), "l"(src));
}
__device__ __forceinline__ void cp_commit() { asm volatile("cp.async.commit_group;"); }
__device__ __forceinline__ void cp_wait1()  { asm volatile("cp.async.wait_group 1;"); }
__device__ __forceinline__ void cp_wait0()  { asm volatile("cp.async.wait_group 0;"); }

__device__ __forceinline__ void mma8(float* c, const uint32_t* a, const uint32_t* b) {
    asm volatile(
        "mma.sync.aligned.m16n8k8.row.col.f32.tf32.tf32.f32 "
        "{%0,%1,%2,%3}, {%4,%5,%6,%7}, {%8,%9}, {%0,%1,%2,%3};"
        : "+f"(c[0]), "+f"(c[1]), "+f"(c[2]), "+f"(c[3])
        : "r"(a[0]), "r"(a[1]), "r"(a[2]), "r"(a[3]), "r"(b[0]), "r"(b[1]));
}

// ---------------- fast w repack: 1 thread per (blk, n) ----------------
__global__ __launch_bounds__(256)
void wt_pack_kernel(const float* __restrict__ wk) {
    const int u = blockIdx.x * 256 + threadIdx.x;   // 0..28671
    const int blk = u / 112;
    const int n = u - blk * 112;
    const int cgO = blk >> 3, gqp = blk & 7;
    const int grp = n / 56, kk = n - grp * 56;
    const int c0 = cgO * 8;
    float* dst = g_wt2 + (size_t)u * 8;

    float o[8];
    if (kk < KK) {
        const float* src = wk + (size_t)((gqp * 2 + grp) * KK + kk) * CH + c0;
        const float4 s0 = *(const float4*)(src);
        const float4 s1 = *(const float4*)(src + 4);
        const float s[8] = {s0.x, s0.y, s0.z, s0.w, s1.x, s1.y, s1.z, s1.w};
        const int xorv = (n >> 2) & 3;
        #pragma unroll
        for (int k8 = 0; k8 < 8; ++k8) {
            const int unit = (k8 & 3) ^ xorv;
            const int half = k8 >> 2;
            o[unit * 2 + half] = __uint_as_float(f2tf32u(s[k8]));
        }
    } else {
        #pragma unroll
        for (int i = 0; i < 8; ++i) o[i] = 0.0f;
    }
    *(float4*)(dst)     = make_float4(o[0], o[1], o[2], o[3]);
    *(float4*)(dst + 4) = make_float4(o[4], o[5], o[6], o[7]);
}

// ---------------- fused main kernel (R9 structure) ----------------
__global__ __launch_bounds__(256, 2)
void invo_main_kernel(const float* __restrict__ x,
                      const float* __restrict__ bk,
                      float* __restrict__ out) {
    extern __shared__ float sm[];
    float* xbuf0 = sm;
    float* xbuf1 = sm + XBUF_F;
    float* wbuf0 = sm + 2 * XBUF_F;
    float* wbuf1 = sm + 2 * XBUF_F + WBUF_F;
    float* k_s   = sm;                      // [slot 98][KROW], aliased after stage 1

    const int t   = threadIdx.x;
    const int rb  = blockIdx.x;
    const int b   = rb >> 5;
    const int h   = (rb & 31) * 2;          // rows h, h+1
    const int gqp = blockIdx.y;             // group pair 0..7

    auto load_chunk = [&](int chunk, int pb) {
        const int c0 = chunk * CC;
        float* xb = pb ? xbuf1 : xbuf0;
        float* wb = pb ? wbuf1 : wbuf0;
        #pragma unroll
        for (int i = 0; i < 4; ++i) {                 // 1024 cp16
            const int u = t + 256 * i;
            const int k = u >> 5;
            const int p4 = (u & 31) << 2;
            cp16(xb + k * PX + (p4 ^ (8 * (k & 3))),
                 x + ((size_t)(b * CH + c0 + k)) * 4096 + h * 64 + p4);
        }
        #pragma unroll
        for (int i = 0; i < 4; ++i) {                 // 896 cp16
            const int u = t + 256 * i;
            if (u < 896) {
                const int cg = u / 224;
                const int r = u - cg * 224;
                cp16(wb + cg * (TAPS * 8) + r * 4,
                     g_wt2 + ((size_t)((chunk * 4 + cg) * 8 + gqp) * TAPS) * 8 + r * 4);
            }
        }
        cp_commit();
    };

    const int wid = t >> 5, lane = t & 31;
    const int la = lane & 3, gid = lane >> 2;
    const int mq = wid & 3, nq = wid >> 2;  // nq 0..1
    const int m0w = mq * 32;
    const int n0w = nq * 56;
    const int sw = 8 * la;

    float acc[2][7][4];
    #pragma unroll
    for (int mt = 0; mt < 2; ++mt)
        #pragma unroll
        for (int nt = 0; nt < 7; ++nt)
            #pragma unroll
            for (int i = 0; i < 4; ++i) acc[mt][nt][i] = 0.0f;

    load_chunk(0, 0);
    for (int ch = 0; ch < NCHUNK; ++ch) {
        const int pb = ch & 1;
        if (ch + 1 < NCHUNK) { load_chunk(ch + 1, pb ^ 1); cp_wait1(); }
        else                 { cp_wait0(); }
        __syncthreads();

        const float* xb = pb ? xbuf1 : xbuf0;
        const float* wb = pb ? wbuf1 : wbuf0;

        #pragma unroll
        for (int ks = 0; ks < 4; ++ks) {
            const int kb = ks * 8;
            uint32_t af[2][4];
            #pragma unroll
            for (int mt = 0; mt < 2; ++mt) {
                const int rm = m0w + mt * 16;
                const int r0 = (rm + gid) ^ sw;
                const int r1 = (rm + 8 + gid) ^ sw;
                af[mt][0] = f2tf32u(xb[(kb + la) * PX + r0]);
                af[mt][1] = f2tf32u(xb[(kb + la) * PX + r1]);
                af[mt][2] = f2tf32u(xb[(kb + la + 4) * PX + r0]);
                af[mt][3] = f2tf32u(xb[(kb + la + 4) * PX + r1]);
            }
            const float* wrow = wb + ks * (TAPS * 8);
            #pragma unroll
            for (int nt = 0; nt < 7; ++nt) {
                const int cn = n0w + nt * 8 + gid;
                const int unit = la ^ ((cn >> 2) & 3);
                const float2 bv = *(const float2*)(wrow + cn * 8 + unit * 2);
                uint32_t bf[2] = {__float_as_uint(bv.x), __float_as_uint(bv.y)};
                mma8(acc[0][nt], af[0], bf);
                mma8(acc[1][nt], af[1], bf);
            }
        }
        __syncthreads();
    }

    // ---- epilogue: bias add, write k_s[slot = nq*49+kk][px] ----
    {
        const int px0 = m0w + gid;
        #pragma unroll
        for (int nt = 0; nt < 7; ++nt) {
            const int kk = nt * 8 + la * 2;
            if (kk < KK) {
                const float bias = bk[(gqp * 2 + nq) * KK + kk];
                const int s = nq * KK + kk;
                k_s[s * KROW + px0]      = acc[0][nt][0] + bias;
                k_s[s * KROW + px0 + 8]  = acc[0][nt][2] + bias;
                k_s[s * KROW + px0 + 16] = acc[1][nt][0] + bias;
                k_s[s * KROW + px0 + 24] = acc[1][nt][2] + bias;
            }
            if (kk + 1 < KK) {
                const float bias1 = bk[(gqp * 2 + nq) * KK + kk + 1];
                const int s1 = nq * KK + kk + 1;
                k_s[s1 * KROW + px0]      = acc[0][nt][1] + bias1;
                k_s[s1 * KROW + px0 + 8]  = acc[0][nt][3] + bias1;
                k_s[s1 * KROW + px0 + 16] = acc[1][nt][1] + bias1;
                k_s[s1 * KROW + px0 + 24] = acc[1][nt][3] + bias1;
            }
        }
    }
    __syncthreads();

    // ---- Stage 2: apply per-pixel 7x7 kernels (fp32) ----
    const int pxg  = t & 15, w0 = pxg << 2;
    const int chq  = (t >> 4) & 3;
    const int grp2 = (t >> 6) & 1;
    const int hrow = t >> 7;
    const int hout = h + hrow;

    float o[4][4];
    #pragma unroll
    for (int m = 0; m < 4; ++m)
        #pragma unroll
        for (int pi = 0; pi < 4; ++pi) o[m][pi] = 0.0f;

    #pragma unroll
    for (int kh = 0; kh < KT; ++kh) {
        const int hh = hout + kh - 3;
        if ((unsigned)hh >= (unsigned)HH) continue;

        float4 kvf[KT];
        #pragma unroll
        for (int kw = 0; kw < KT; ++kw)
            kvf[kw] = *(const float4*)&k_s[(grp2 * KK + kh * KT + kw) * KROW + hrow * 64 + w0];

        #pragma unroll
        for (int m = 0; m < 4; ++m) {
            const int c = gqp * 32 + grp2 * 16 + chq + (m << 2);
            const float* xr = x + ((size_t)(b * CH + c) * HH + hh) * WW;
            const float4 A = (pxg >= 1)  ? *(const float4*)(xr + w0 - 4)
                                         : make_float4(0.f, 0.f, 0.f, 0.f);
            const float4 Bv = *(const float4*)(xr + w0);
            const float4 Cc = (pxg <= 14) ? *(const float4*)(xr + w0 + 4)
                                          : make_float4(0.f, 0.f, 0.f, 0.f);
            const float xv[10] = {A.y, A.z, A.w, Bv.x, Bv.y, Bv.z, Bv.w, Cc.x, Cc.y, Cc.z};
            #pragma unroll
            for (int kw = 0; kw < KT; ++kw) {
                o[m][0] += xv[kw]     * kvf[kw].x;
                o[m][1] += xv[kw + 1] * kvf[kw].y;
                o[m][2] += xv[kw + 2] * kvf[kw].z;
                o[m][3] += xv[kw + 3] * kvf[kw].w;
            }
        }
    }

    #pragma unroll
    for (int m = 0; m < 4; ++m) {
        const int c = gqp * 32 + grp2 * 16 + chq + (m << 2);
        *reinterpret_cast<float4*>(out + ((size_t)(b * CH + c) * HH + hout) * WW + w0) =
            make_float4(o[m][0], o[m][1], o[m][2], o[m][3]);
    }
}

extern "C" void kernel_launch(void* const* d_in, const int* in_sizes, int n_in,
                              void* d_out, int out_size) {
    const float* x  = (const float*)d_in[0];
    const float* wk = (const float*)d_in[1];
    const float* bk = (const float*)d_in[2];
    float* out      = (float*)d_out;

    wt_pack_kernel<<<112, 256>>>(wk);

    cudaFuncSetAttribute(invo_main_kernel,
                         cudaFuncAttributeMaxDynamicSharedMemorySize, SMEM_BYTES);
    dim3 grid(4 * 32, 8);               // (b*hpair, gq-pair) = (128, 8) = 1024 blocks
    invo_main_kernel<<<grid, 256, SMEM_BYTES>>>(x, bk, out);
}

// round 14
// speedup vs baseline: 1.8801x; 1.2415x over previous
#include <cuda_runtime.h>
#include <cuda_fp16.h>
#include <cstdint>

// Involution2d on GB300 (sm_103 base ISA). B=4, C=256, H=W=64, G=16, K=7, PAD=3.
// R14 = R13 (fp16 m16n8k16 stage 1) with the half2->uint bit-cast fixed.

#define CH 256
#define HH 64
#define WW 64
#define KT 7
#define KK 49
#define CC 32                  // channels per chunk (= 16 channel-pairs)
#define NCHUNK 8
#define PX 128                 // pixels per block (2 rows)
#define KROW 132               // k_s row stride, 132%32=4 -> conflict-free
#define WROW 128               // w_s row width (padded from 112, XOR-safe)

#define XBUF_U 2048            // 16 kp * 128 px  (uint32 = half2)
#define WBUF_U 2048            // 16 kp * 128 n   (uint32 = half2)
#define KS_BYTES (98 * KROW * 4)                 // 51744
#define SMEM_BYTES KS_BYTES                      // buffers need 32768 < 51744

// packed inputs
__device__ uint32_t g_xh[4 * 128 * 4096];        // [b][cpair][px] half2
__device__ uint32_t g_wh[8 * 8 * 16 * WROW];     // [chunk][gqp][kp][n^8*(kp&3)] half2

// ---------------- helpers ----------------
__device__ __forceinline__ uint32_t h2u(__half2 h) {
    uint32_t u;
    memcpy(&u, &h, 4);
    return u;
}
__device__ __forceinline__ void cp16(void* dst, const void* src) {
    unsigned sa = (unsigned)__cvta_generic_to_shared(dst);
    asm volatile("cp.async.cg.shared.global [%0], [%1], 16;" :: "r"(sa), "l"(src));
}
__device__ __forceinline__ void cp_commit() { asm volatile("cp.async.commit_group;"); }
__device__ __forceinline__ void cp_wait1()  { asm volatile("cp.async.wait_group 1;"); }
__device__ __forceinline__ void cp_wait0()  { asm volatile("cp.async.wait_group 0;"); }

__device__ __forceinline__ void mma16(float* c, const uint32_t* a, const uint32_t* b) {
    asm volatile(
        "mma.sync.aligned.m16n8k16.row.col.f32.f16.f16.f32 "
        "{%0,%1,%2,%3}, {%4,%5,%6,%7}, {%8,%9}, {%0,%1,%2,%3};"
        : "+f"(c[0]), "+f"(c[1]), "+f"(c[2]), "+f"(c[3])
        : "r"(a[0]), "r"(a[1]), "r"(a[2]), "r"(a[3]), "r"(b[0]), "r"(b[1]));
}

// ---------------- x pack: fp32 [b][c][px] -> half2 [b][cpair][px] ----------------
__global__ __launch_bounds__(256)
void x_pack_kernel(const float* __restrict__ x) {
    const int u = blockIdx.x * 256 + threadIdx.x;     // 0..524287
    const int px4 = (u & 1023) << 2;
    const int cp  = (u >> 10) & 127;
    const int b   = u >> 17;
    const float4 a0 = *(const float4*)(x + ((size_t)(b * CH + 2 * cp)) * 4096 + px4);
    const float4 a1 = *(const float4*)(x + ((size_t)(b * CH + 2 * cp + 1)) * 4096 + px4);
    uint32_t o[4];
    o[0] = h2u(__floats2half2_rn(a0.x, a1.x));
    o[1] = h2u(__floats2half2_rn(a0.y, a1.y));
    o[2] = h2u(__floats2half2_rn(a0.z, a1.z));
    o[3] = h2u(__floats2half2_rn(a0.w, a1.w));
    *(uint4*)(g_xh + ((size_t)(b * 128 + cp)) * 4096 + px4) = make_uint4(o[0], o[1], o[2], o[3]);
}

// ---------------- w pack: fp32 -> half2, XOR baked, taps padded ----------------
__global__ __launch_bounds__(256)
void wt_pack_kernel(const float* __restrict__ wk) {
    const int u = blockIdx.x * 256 + threadIdx.x;     // 0..131071
    const int nslot = u & 127;
    const int kp    = (u >> 7) & 15;
    const int gqp   = (u >> 11) & 7;
    const int chunk = u >> 14;
    const int nlog  = nslot ^ (8 * (kp & 3));          // logical n this slot holds
    const int grp = nlog / 56, kk = nlog - grp * 56;
    uint32_t v = 0;
    if (nlog < 112 && kk < KK) {
        const int c = chunk * CC + 2 * kp;
        const float* src = wk + (size_t)((gqp * 2 + grp) * KK + kk) * CH + c;
        v = h2u(__floats2half2_rn(src[0], src[1]));
    }
    g_wh[u] = v;
}

// ---------------- fused main kernel ----------------
__global__ __launch_bounds__(256, 2)
void invo_main_kernel(const float* __restrict__ x,
                      const float* __restrict__ bk,
                      float* __restrict__ out) {
    extern __shared__ float sm[];
    uint32_t* smu = (uint32_t*)sm;
    float* k_s = sm;                        // [slot 98][KROW], aliased after stage 1

    const int t   = threadIdx.x;
    const int rb  = blockIdx.x;
    const int b   = rb >> 5;
    const int h   = (rb & 31) * 2;          // rows h, h+1
    const int gqp = blockIdx.y;

    auto xbuf = [&](int p) { return smu + p * XBUF_U; };
    auto wbuf = [&](int p) { return smu + 2 * XBUF_U + p * WBUF_U; };

    // ---- chunk loader ----
    auto load_chunk = [&](int chunk, int pb) {
        uint32_t* xb = xbuf(pb);
        uint32_t* wb = wbuf(pb);
        #pragma unroll
        for (int i = 0; i < 2; ++i) {                 // 512 cp16
            const int u = t + 256 * i;
            const int kp = u >> 5;
            const int p4 = (u & 31) << 2;
            cp16(xb + kp * 128 + (p4 ^ (8 * (kp & 3))),
                 g_xh + ((size_t)(b * 128 + chunk * 16 + kp)) * 4096 + h * 64 + p4);
        }
        const uint32_t* wsrc = g_wh + ((size_t)(chunk * 8 + gqp)) * (16 * WROW);
        #pragma unroll
        for (int i = 0; i < 2; ++i) {                 // 512 cp16, linear
            const int u = t + 256 * i;
            cp16(wb + u * 4, wsrc + u * 4);
        }
        cp_commit();
    };

    // ---- Stage 1: mma.sync fp16, 8 warps, warp tile m32 x n56 ----
    const int wid = t >> 5, lane = t & 31;
    const int la = lane & 3, gid = lane >> 2;
    const int mq = wid & 3, nq = wid >> 2;  // nq 0..1
    const int m0w = mq * 32;
    const int n0w = nq * 56;
    const int sw = 8 * la;

    float acc[2][7][4];
    #pragma unroll
    for (int mt = 0; mt < 2; ++mt)
        #pragma unroll
        for (int nt = 0; nt < 7; ++nt)
            #pragma unroll
            for (int i = 0; i < 4; ++i) acc[mt][nt][i] = 0.0f;

    load_chunk(0, 0);
    for (int ch = 0; ch < NCHUNK; ++ch) {
        const int pb = ch & 1;
        if (ch + 1 < NCHUNK) { load_chunk(ch + 1, pb ^ 1); cp_wait1(); }
        else                 { cp_wait0(); }
        __syncthreads();

        const uint32_t* xb = xbuf(pb);
        const uint32_t* wb = wbuf(pb);

        #pragma unroll
        for (int ks = 0; ks < 2; ++ks) {              // 2 x K=16 per chunk
            const int kbp = ks * 8;                   // kpair base
            uint32_t af[2][4];
            #pragma unroll
            for (int mt = 0; mt < 2; ++mt) {
                const int rm = m0w + mt * 16;
                const int r0 = (rm + gid) ^ sw;
                const int r1 = (rm + 8 + gid) ^ sw;
                af[mt][0] = xb[(kbp + la) * 128 + r0];      // k[0:8) rows gid
                af[mt][1] = xb[(kbp + la) * 128 + r1];      //        rows gid+8
                af[mt][2] = xb[(kbp + la + 4) * 128 + r0];  // k[8:16)
                af[mt][3] = xb[(kbp + la + 4) * 128 + r1];
            }
            const uint32_t* wrow0 = wb + (kbp + la) * WROW;
            const uint32_t* wrow1 = wb + (kbp + la + 4) * WROW;
            #pragma unroll
            for (int nt = 0; nt < 7; ++nt) {
                const int cn = (n0w + nt * 8 + gid) ^ sw;
                uint32_t bf[2] = {wrow0[cn], wrow1[cn]};
                mma16(acc[0][nt], af[0], bf);
                mma16(acc[1][nt], af[1], bf);
            }
        }
        __syncthreads();
    }

    // ---- epilogue: bias add, write k_s[slot = nq*49+kk][px] ----
    {
        const int px0 = m0w + gid;
        #pragma unroll
        for (int nt = 0; nt < 7; ++nt) {
            const int kk = nt * 8 + la * 2;
            if (kk < KK) {
                const float bias = bk[(gqp * 2 + nq) * KK + kk];
                const int s = nq * KK + kk;
                k_s[s * KROW + px0]      = acc[0][nt][0] + bias;
                k_s[s * KROW + px0 + 8]  = acc[0][nt][2] + bias;
                k_s[s * KROW + px0 + 16] = acc[1][nt][0] + bias;
                k_s[s * KROW + px0 + 24] = acc[1][nt][2] + bias;
            }
            if (kk + 1 < KK) {
                const float bias1 = bk[(gqp * 2 + nq) * KK + kk + 1];
                const int s1 = nq * KK + kk + 1;
                k_s[s1 * KROW + px0]      = acc[0][nt][1] + bias1;
                k_s[s1 * KROW + px0 + 8]  = acc[0][nt][3] + bias1;
                k_s[s1 * KROW + px0 + 16] = acc[1][nt][1] + bias1;
                k_s[s1 * KROW + px0 + 24] = acc[1][nt][3] + bias1;
            }
        }
    }
    __syncthreads();

    // ---- Stage 2: apply per-pixel 7x7 kernels (fp32) ----
    const int pxg  = t & 15, w0 = pxg << 2;
    const int chq  = (t >> 4) & 3;
    const int grp2 = (t >> 6) & 1;
    const int hrow = t >> 7;
    const int hout = h + hrow;

    float o[4][4];
    #pragma unroll
    for (int m = 0; m < 4; ++m)
        #pragma unroll
        for (int pi = 0; pi < 4; ++pi) o[m][pi] = 0.0f;

    #pragma unroll
    for (int kh = 0; kh < KT; ++kh) {
        const int hh = hout + kh - 3;
        if ((unsigned)hh >= (unsigned)HH) continue;

        float4 kvf[KT];
        #pragma unroll
        for (int kw = 0; kw < KT; ++kw)
            kvf[kw] = *(const float4*)&k_s[(grp2 * KK + kh * KT + kw) * KROW + hrow * 64 + w0];

        #pragma unroll
        for (int m = 0; m < 4; ++m) {
            const int c = gqp * 32 + grp2 * 16 + chq + (m << 2);
            const float* xr = x + ((size_t)(b * CH + c) * HH + hh) * WW;
            const float4 A = (pxg >= 1)  ? *(const float4*)(xr + w0 - 4)
                                         : make_float4(0.f, 0.f, 0.f, 0.f);
            const float4 Bv = *(const float4*)(xr + w0);
            const float4 Cc = (pxg <= 14) ? *(const float4*)(xr + w0 + 4)
                                          : make_float4(0.f, 0.f, 0.f, 0.f);
            const float xv[10] = {A.y, A.z, A.w, Bv.x, Bv.y, Bv.z, Bv.w, Cc.x, Cc.y, Cc.z};
            #pragma unroll
            for (int kw = 0; kw < KT; ++kw) {
                o[m][0] += xv[kw]     * kvf[kw].x;
                o[m][1] += xv[kw + 1] * kvf[kw].y;
                o[m][2] += xv[kw + 2] * kvf[kw].z;
                o[m][3] += xv[kw + 3] * kvf[kw].w;
            }
        }
    }

    #pragma unroll
    for (int m = 0; m < 4; ++m) {
        const int c = gqp * 32 + grp2 * 16 + chq + (m << 2);
        *reinterpret_cast<float4*>(out + ((size_t)(b * CH + c) * HH + hout) * WW + w0) =
            make_float4(o[m][0], o[m][1], o[m][2], o[m][3]);
    }
}

extern "C" void kernel_launch(void* const* d_in, const int* in_sizes, int n_in,
                              void* d_out, int out_size) {
    const float* x  = (const float*)d_in[0];
    const float* wk = (const float*)d_in[1];
    const float* bk = (const float*)d_in[2];
    float* out      = (float*)d_out;

    x_pack_kernel<<<2048, 256>>>(x);
    wt_pack_kernel<<<512, 256>>>(wk);

    cudaFuncSetAttribute(invo_main_kernel,
                         cudaFuncAttributeMaxDynamicSharedMemorySize, SMEM_BYTES);
    dim3 grid(4 * 32, 8);               // (b*hpair, gq-pair) = (128, 8) = 1024 blocks
    invo_main_kernel<<<grid, 256, SMEM_BYTES>>>(x, bk, out);
}

// round 15
// speedup vs baseline: 2.0253x; 1.0773x over previous
#include <cuda_runtime.h>
#include <cuda_fp16.h>
#include <cstdint>

// Involution2d on GB300 (sm_103 base ISA). B=4, C=256, H=W=64, G=16, K=7, PAD=3.
// R15 = R14 + stage 2 reads packed fp16 x (2 channels per load, half the LDGs).

#define CH 256
#define HH 64
#define WW 64
#define KT 7
#define KK 49
#define CC 32                  // channels per chunk (= 16 channel-pairs)
#define NCHUNK 8
#define PX 128                 // pixels per block (2 rows)
#define KROW 132               // k_s row stride, 132%32=4 -> conflict-free
#define WROW 128               // w_s row width (padded from 112, XOR-safe)

#define XBUF_U 2048            // 16 kp * 128 px  (uint32 = half2)
#define WBUF_U 2048            // 16 kp * 128 n   (uint32 = half2)
#define KS_BYTES (98 * KROW * 4)                 // 51744
#define SMEM_BYTES KS_BYTES

// packed inputs
__device__ uint32_t g_xh[4 * 128 * 4096];        // [b][cpair][px] half2 = (x[2cp], x[2cp+1])
__device__ uint32_t g_wh[8 * 8 * 16 * WROW];     // [chunk][gqp][kp][n^8*(kp&3)] half2

// ---------------- helpers ----------------
__device__ __forceinline__ uint32_t h2u(__half2 h) {
    uint32_t u;
    memcpy(&u, &h, 4);
    return u;
}
__device__ __forceinline__ float2 u2f2(uint32_t u) {
    __half2 h;
    memcpy(&h, &u, 4);
    return __half22float2(h);
}
__device__ __forceinline__ void cp16(void* dst, const void* src) {
    unsigned sa = (unsigned)__cvta_generic_to_shared(dst);
    asm volatile("cp.async.cg.shared.global [%0], [%1], 16;" :: "r"(sa), "l"(src));
}
__device__ __forceinline__ void cp_commit() { asm volatile("cp.async.commit_group;"); }
__device__ __forceinline__ void cp_wait1()  { asm volatile("cp.async.wait_group 1;"); }
__device__ __forceinline__ void cp_wait0()  { asm volatile("cp.async.wait_group 0;"); }

__device__ __forceinline__ void mma16(float* c, const uint32_t* a, const uint32_t* b) {
    asm volatile(
        "mma.sync.aligned.m16n8k16.row.col.f32.f16.f16.f32 "
        "{%0,%1,%2,%3}, {%4,%5,%6,%7}, {%8,%9}, {%0,%1,%2,%3};"
        : "+f"(c[0]), "+f"(c[1]), "+f"(c[2]), "+f"(c[3])
        : "r"(a[0]), "r"(a[1]), "r"(a[2]), "r"(a[3]), "r"(b[0]), "r"(b[1]));
}

// ---------------- x pack: fp32 [b][c][px] -> half2 [b][cpair][px] ----------------
__global__ __launch_bounds__(256)
void x_pack_kernel(const float* __restrict__ x) {
    const int u = blockIdx.x * 256 + threadIdx.x;     // 0..524287
    const int px4 = (u & 1023) << 2;
    const int cp  = (u >> 10) & 127;
    const int b   = u >> 17;
    const float4 a0 = *(const float4*)(x + ((size_t)(b * CH + 2 * cp)) * 4096 + px4);
    const float4 a1 = *(const float4*)(x + ((size_t)(b * CH + 2 * cp + 1)) * 4096 + px4);
    uint32_t o[4];
    o[0] = h2u(__floats2half2_rn(a0.x, a1.x));
    o[1] = h2u(__floats2half2_rn(a0.y, a1.y));
    o[2] = h2u(__floats2half2_rn(a0.z, a1.z));
    o[3] = h2u(__floats2half2_rn(a0.w, a1.w));
    *(uint4*)(g_xh + ((size_t)(b * 128 + cp)) * 4096 + px4) = make_uint4(o[0], o[1], o[2], o[3]);
}

// ---------------- w pack: fp32 -> half2, XOR baked, taps padded ----------------
__global__ __launch_bounds__(256)
void wt_pack_kernel(const float* __restrict__ wk) {
    const int u = blockIdx.x * 256 + threadIdx.x;     // 0..131071
    const int nslot = u & 127;
    const int kp    = (u >> 7) & 15;
    const int gqp   = (u >> 11) & 7;
    const int chunk = u >> 14;
    const int nlog  = nslot ^ (8 * (kp & 3));
    const int grp = nlog / 56, kk = nlog - grp * 56;
    uint32_t v = 0;
    if (nlog < 112 && kk < KK) {
        const int c = chunk * CC + 2 * kp;
        const float* src = wk + (size_t)((gqp * 2 + grp) * KK + kk) * CH + c;
        v = h2u(__floats2half2_rn(src[0], src[1]));
    }
    g_wh[u] = v;
}

// ---------------- fused main kernel ----------------
__global__ __launch_bounds__(256, 2)
void invo_main_kernel(const float* __restrict__ bk,
                      float* __restrict__ out) {
    extern __shared__ float sm[];
    uint32_t* smu = (uint32_t*)sm;
    float* k_s = sm;                        // [slot 98][KROW], aliased after stage 1

    const int t   = threadIdx.x;
    const int rb  = blockIdx.x;
    const int b   = rb >> 5;
    const int h   = (rb & 31) * 2;          // rows h, h+1
    const int gqp = blockIdx.y;

    auto xbuf = [&](int p) { return smu + p * XBUF_U; };
    auto wbuf = [&](int p) { return smu + 2 * XBUF_U + p * WBUF_U; };

    auto load_chunk = [&](int chunk, int pb) {
        uint32_t* xb = xbuf(pb);
        uint32_t* wb = wbuf(pb);
        #pragma unroll
        for (int i = 0; i < 2; ++i) {                 // 512 cp16
            const int u = t + 256 * i;
            const int kp = u >> 5;
            const int p4 = (u & 31) << 2;
            cp16(xb + kp * 128 + (p4 ^ (8 * (kp & 3))),
                 g_xh + ((size_t)(b * 128 + chunk * 16 + kp)) * 4096 + h * 64 + p4);
        }
        const uint32_t* wsrc = g_wh + ((size_t)(chunk * 8 + gqp)) * (16 * WROW);
        #pragma unroll
        for (int i = 0; i < 2; ++i) {                 // 512 cp16, linear
            const int u = t + 256 * i;
            cp16(wb + u * 4, wsrc + u * 4);
        }
        cp_commit();
    };

    // ---- Stage 1: mma.sync fp16, 8 warps, warp tile m32 x n56 ----
    const int wid = t >> 5, lane = t & 31;
    const int la = lane & 3, gid = lane >> 2;
    const int mq = wid & 3, nq = wid >> 2;
    const int m0w = mq * 32;
    const int n0w = nq * 56;
    const int sw = 8 * la;

    float acc[2][7][4];
    #pragma unroll
    for (int mt = 0; mt < 2; ++mt)
        #pragma unroll
        for (int nt = 0; nt < 7; ++nt)
            #pragma unroll
            for (int i = 0; i < 4; ++i) acc[mt][nt][i] = 0.0f;

    load_chunk(0, 0);
    for (int ch = 0; ch < NCHUNK; ++ch) {
        const int pb = ch & 1;
        if (ch + 1 < NCHUNK) { load_chunk(ch + 1, pb ^ 1); cp_wait1(); }
        else                 { cp_wait0(); }
        __syncthreads();

        const uint32_t* xb = xbuf(pb);
        const uint32_t* wb = wbuf(pb);

        #pragma unroll
        for (int ks = 0; ks < 2; ++ks) {
            const int kbp = ks * 8;
            uint32_t af[2][4];
            #pragma unroll
            for (int mt = 0; mt < 2; ++mt) {
                const int rm = m0w + mt * 16;
                const int r0 = (rm + gid) ^ sw;
                const int r1 = (rm + 8 + gid) ^ sw;
                af[mt][0] = xb[(kbp + la) * 128 + r0];
                af[mt][1] = xb[(kbp + la) * 128 + r1];
                af[mt][2] = xb[(kbp + la + 4) * 128 + r0];
                af[mt][3] = xb[(kbp + la + 4) * 128 + r1];
            }
            const uint32_t* wrow0 = wb + (kbp + la) * WROW;
            const uint32_t* wrow1 = wb + (kbp + la + 4) * WROW;
            #pragma unroll
            for (int nt = 0; nt < 7; ++nt) {
                const int cn = (n0w + nt * 8 + gid) ^ sw;
                uint32_t bf[2] = {wrow0[cn], wrow1[cn]};
                mma16(acc[0][nt], af[0], bf);
                mma16(acc[1][nt], af[1], bf);
            }
        }
        __syncthreads();
    }

    // ---- epilogue: bias add, write k_s[slot = nq*49+kk][px] ----
    {
        const int px0 = m0w + gid;
        #pragma unroll
        for (int nt = 0; nt < 7; ++nt) {
            const int kk = nt * 8 + la * 2;
            if (kk < KK) {
                const float bias = bk[(gqp * 2 + nq) * KK + kk];
                const int s = nq * KK + kk;
                k_s[s * KROW + px0]      = acc[0][nt][0] + bias;
                k_s[s * KROW + px0 + 8]  = acc[0][nt][2] + bias;
                k_s[s * KROW + px0 + 16] = acc[1][nt][0] + bias;
                k_s[s * KROW + px0 + 24] = acc[1][nt][2] + bias;
            }
            if (kk + 1 < KK) {
                const float bias1 = bk[(gqp * 2 + nq) * KK + kk + 1];
                const int s1 = nq * KK + kk + 1;
                k_s[s1 * KROW + px0]      = acc[0][nt][1] + bias1;
                k_s[s1 * KROW + px0 + 8]  = acc[0][nt][3] + bias1;
                k_s[s1 * KROW + px0 + 16] = acc[1][nt][1] + bias1;
                k_s[s1 * KROW + px0 + 24] = acc[1][nt][3] + bias1;
            }
        }
    }
    __syncthreads();

    // ---- Stage 2: per-pixel 7x7 kernels; x from g_xh (2 channels per half2) ----
    const int pxg  = t & 15, w0 = pxg << 2;
    const int chq  = (t >> 4) & 3;          // cpair selector within group (0..3)
    const int grp2 = (t >> 6) & 1;
    const int hrow = t >> 7;
    const int hout = h + hrow;
    const int grpG = gqp * 2 + grp2;        // global group

    float o[2][2][4];                       // [cpair-half mp][ch of pair][pi]
    #pragma unroll
    for (int mp = 0; mp < 2; ++mp)
        #pragma unroll
        for (int cc2 = 0; cc2 < 2; ++cc2)
            #pragma unroll
            for (int pi = 0; pi < 4; ++pi) o[mp][cc2][pi] = 0.0f;

    #pragma unroll
    for (int kh = 0; kh < KT; ++kh) {
        const int hh = hout + kh - 3;
        if ((unsigned)hh >= (unsigned)HH) continue;

        float4 kvf[KT];
        #pragma unroll
        for (int kw = 0; kw < KT; ++kw)
            kvf[kw] = *(const float4*)&k_s[(grp2 * KK + kh * KT + kw) * KROW + hrow * 64 + w0];

        #pragma unroll
        for (int mp = 0; mp < 2; ++mp) {
            const int cp = grpG * 8 + chq + mp * 4;     // global cpair
            const uint32_t* xr = g_xh + ((size_t)(b * 128 + cp)) * 4096 + hh * 64;
            uint4 A  = make_uint4(0, 0, 0, 0);
            uint4 Bv = *(const uint4*)(xr + w0);
            uint4 Cc = make_uint4(0, 0, 0, 0);
            if (pxg >= 1)  A  = *(const uint4*)(xr + w0 - 4);
            if (pxg <= 14) Cc = *(const uint4*)(xr + w0 + 4);
            float2 xv[10];
            xv[0] = u2f2(A.y);  xv[1] = u2f2(A.z);  xv[2] = u2f2(A.w);
            xv[3] = u2f2(Bv.x); xv[4] = u2f2(Bv.y); xv[5] = u2f2(Bv.z); xv[6] = u2f2(Bv.w);
            xv[7] = u2f2(Cc.x); xv[8] = u2f2(Cc.y); xv[9] = u2f2(Cc.z);
            #pragma unroll
            for (int kw = 0; kw < KT; ++kw) {
                const float kv0 = kvf[kw].x, kv1 = kvf[kw].y;
                const float kv2 = kvf[kw].z, kv3 = kvf[kw].w;
                o[mp][0][0] += xv[kw].x     * kv0;  o[mp][1][0] += xv[kw].y     * kv0;
                o[mp][0][1] += xv[kw + 1].x * kv1;  o[mp][1][1] += xv[kw + 1].y * kv1;
                o[mp][0][2] += xv[kw + 2].x * kv2;  o[mp][1][2] += xv[kw + 2].y * kv2;
                o[mp][0][3] += xv[kw + 3].x * kv3;  o[mp][1][3] += xv[kw + 3].y * kv3;
            }
        }
    }

    #pragma unroll
    for (int mp = 0; mp < 2; ++mp) {
        const int cp = grpG * 8 + chq + mp * 4;
        #pragma unroll
        for (int cc2 = 0; cc2 < 2; ++cc2) {
            const int c = 2 * cp + cc2;
            *reinterpret_cast<float4*>(out + ((size_t)(b * CH + c) * HH + hout) * WW + w0) =
                make_float4(o[mp][cc2][0], o[mp][cc2][1], o[mp][cc2][2], o[mp][cc2][3]);
        }
    }
}

extern "C" void kernel_launch(void* const* d_in, const int* in_sizes, int n_in,
                              void* d_out, int out_size) {
    const float* x  = (const float*)d_in[0];
    const float* wk = (const float*)d_in[1];
    const float* bk = (const float*)d_in[2];
    float* out      = (float*)d_out;

    x_pack_kernel<<<2048, 256>>>(x);
    wt_pack_kernel<<<512, 256>>>(wk);

    cudaFuncSetAttribute(invo_main_kernel,
                         cudaFuncAttributeMaxDynamicSharedMemorySize, SMEM_BYTES);
    dim3 grid(4 * 32, 8);               // (b*hpair, gq-pair) = (128, 8) = 1024 blocks
    invo_main_kernel<<<grid, 256, SMEM_BYTES>>>(bk, out);
}

// round 16
// speedup vs baseline: 2.1128x; 1.0432x over previous
#include <cuda_runtime.h>
#include <cuda_fp16.h>
#include <cstdint>

// Involution2d on GB300 (sm_103 base ISA). B=4, C=256, H=W=64, G=16, K=7, PAD=3.
// R16 = R15 + CC=64 chunks (half the barriers) + ILP-tuned x_pack.

#define CH 256
#define HH 64
#define WW 64
#define KT 7
#define KK 49
#define CC 64                  // channels per chunk (= 32 channel-pairs)
#define NCHUNK 4
#define PX 128                 // pixels per block (2 rows)
#define KROW 132               // k_s row stride, 132%32=4 -> conflict-free
#define WROW 128               // w_s row width (padded from 112, XOR-safe)

#define XBUF_U 4096            // 32 kp * 128 px  (uint32 = half2)
#define WBUF_U 4096            // 32 kp * 128 n
#define SMEM_BYTES (2 * (XBUF_U + WBUF_U) * 4)   // 65536; k_s alias 51744 fits

// packed inputs
__device__ uint32_t g_xh[4 * 128 * 4096];        // [b][cpair][px] half2 = (x[2cp], x[2cp+1])
__device__ uint32_t g_wh[8 * 128 * WROW];        // [gqp][kpG][n ^ 8*(kpG&3)] half2

// ---------------- helpers ----------------
__device__ __forceinline__ uint32_t h2u(__half2 h) {
    uint32_t u;
    memcpy(&u, &h, 4);
    return u;
}
__device__ __forceinline__ float2 u2f2(uint32_t u) {
    __half2 h;
    memcpy(&h, &u, 4);
    return __half22float2(h);
}
__device__ __forceinline__ void cp16(void* dst, const void* src) {
    unsigned sa = (unsigned)__cvta_generic_to_shared(dst);
    asm volatile("cp.async.cg.shared.global [%0], [%1], 16;" :: "r"(sa), "l"(src));
}
__device__ __forceinline__ void cp_commit() { asm volatile("cp.async.commit_group;"); }
__device__ __forceinline__ void cp_wait1()  { asm volatile("cp.async.wait_group 1;"); }
__device__ __forceinline__ void cp_wait0()  { asm volatile("cp.async.wait_group 0;"); }

__device__ __forceinline__ void mma16(float* c, const uint32_t* a, const uint32_t* b) {
    asm volatile(
        "mma.sync.aligned.m16n8k16.row.col.f32.f16.f16.f32 "
        "{%0,%1,%2,%3}, {%4,%5,%6,%7}, {%8,%9}, {%0,%1,%2,%3};"
        : "+f"(c[0]), "+f"(c[1]), "+f"(c[2]), "+f"(c[3])
        : "r"(a[0]), "r"(a[1]), "r"(a[2]), "r"(a[3]), "r"(b[0]), "r"(b[1]));
}

// ---------------- x pack: fp32 [b][c][px] -> half2 [b][cpair][px], 2 units/thread ----
__global__ __launch_bounds__(256)
void x_pack_kernel(const float* __restrict__ x) {
    const int base = blockIdx.x * 512 + threadIdx.x;
    #pragma unroll
    for (int j = 0; j < 2; ++j) {
        const int u = base + j * 256;                 // 0..524287
        const int px4 = (u & 1023) << 2;
        const int cp  = (u >> 10) & 127;
        const int b   = u >> 17;
        const float4 a0 = *(const float4*)(x + ((size_t)(b * CH + 2 * cp)) * 4096 + px4);
        const float4 a1 = *(const float4*)(x + ((size_t)(b * CH + 2 * cp + 1)) * 4096 + px4);
        uint32_t o[4];
        o[0] = h2u(__floats2half2_rn(a0.x, a1.x));
        o[1] = h2u(__floats2half2_rn(a0.y, a1.y));
        o[2] = h2u(__floats2half2_rn(a0.z, a1.z));
        o[3] = h2u(__floats2half2_rn(a0.w, a1.w));
        *(uint4*)(g_xh + ((size_t)(b * 128 + cp)) * 4096 + px4) =
            make_uint4(o[0], o[1], o[2], o[3]);
    }
}

// ---------------- w pack: fp32 -> half2, XOR baked, taps padded ----------------
__global__ __launch_bounds__(256)
void wt_pack_kernel(const float* __restrict__ wk) {
    const int u = blockIdx.x * 256 + threadIdx.x;     // 0..131071
    const int nslot = u & 127;
    const int kpG   = (u >> 7) & 127;
    const int gqp   = u >> 14;
    const int nlog  = nslot ^ (8 * (kpG & 3));
    const int grp = nlog / 56, kk = nlog - grp * 56;
    uint32_t v = 0;
    if (nlog < 112 && kk < KK) {
        const int c = 2 * kpG;
        const float* src = wk + (size_t)((gqp * 2 + grp) * KK + kk) * CH + c;
        v = h2u(__floats2half2_rn(src[0], src[1]));
    }
    g_wh[u] = v;
}

// ---------------- fused main kernel ----------------
__global__ __launch_bounds__(256, 2)
void invo_main_kernel(const float* __restrict__ bk,
                      float* __restrict__ out) {
    extern __shared__ float sm[];
    uint32_t* smu = (uint32_t*)sm;
    float* k_s = sm;                        // [slot 98][KROW], aliased after stage 1

    const int t   = threadIdx.x;
    const int rb  = blockIdx.x;
    const int b   = rb >> 5;
    const int h   = (rb & 31) * 2;          // rows h, h+1
    const int gqp = blockIdx.y;

    auto xbuf = [&](int p) { return smu + p * XBUF_U; };
    auto wbuf = [&](int p) { return smu + 2 * XBUF_U + p * WBUF_U; };

    auto load_chunk = [&](int chunk, int pb) {
        uint32_t* xb = xbuf(pb);
        uint32_t* wb = wbuf(pb);
        #pragma unroll
        for (int i = 0; i < 4; ++i) {                 // 1024 cp16
            const int u = t + 256 * i;
            const int kp = u >> 5;                    // 0..31
            const int p4 = (u & 31) << 2;
            cp16(xb + kp * 128 + (p4 ^ (8 * (kp & 3))),
                 g_xh + ((size_t)(b * 128 + chunk * 32 + kp)) * 4096 + h * 64 + p4);
        }
        const uint32_t* wsrc = g_wh + ((size_t)gqp * 128 + chunk * 32) * WROW;
        #pragma unroll
        for (int i = 0; i < 4; ++i) {                 // 1024 cp16, linear
            const int u = t + 256 * i;
            cp16(wb + u * 4, wsrc + u * 4);
        }
        cp_commit();
    };

    // ---- Stage 1: mma.sync fp16, 8 warps, warp tile m32 x n56 ----
    const int wid = t >> 5, lane = t & 31;
    const int la = lane & 3, gid = lane >> 2;
    const int mq = wid & 3, nq = wid >> 2;
    const int m0w = mq * 32;
    const int n0w = nq * 56;
    const int sw = 8 * la;

    float acc[2][7][4];
    #pragma unroll
    for (int mt = 0; mt < 2; ++mt)
        #pragma unroll
        for (int nt = 0; nt < 7; ++nt)
            #pragma unroll
            for (int i = 0; i < 4; ++i) acc[mt][nt][i] = 0.0f;

    load_chunk(0, 0);
    for (int ch = 0; ch < NCHUNK; ++ch) {
        const int pb = ch & 1;
        if (ch + 1 < NCHUNK) { load_chunk(ch + 1, pb ^ 1); cp_wait1(); }
        else                 { cp_wait0(); }
        __syncthreads();

        const uint32_t* xb = xbuf(pb);
        const uint32_t* wb = wbuf(pb);

        #pragma unroll
        for (int ks = 0; ks < 4; ++ks) {              // 4 x K=16 per chunk
            const int kbp = ks * 8;
            uint32_t af[2][4];
            #pragma unroll
            for (int mt = 0; mt < 2; ++mt) {
                const int rm = m0w + mt * 16;
                const int r0 = (rm + gid) ^ sw;
                const int r1 = (rm + 8 + gid) ^ sw;
                af[mt][0] = xb[(kbp + la) * 128 + r0];
                af[mt][1] = xb[(kbp + la) * 128 + r1];
                af[mt][2] = xb[(kbp + la + 4) * 128 + r0];
                af[mt][3] = xb[(kbp + la + 4) * 128 + r1];
            }
            const uint32_t* wrow0 = wb + (kbp + la) * WROW;
            const uint32_t* wrow1 = wb + (kbp + la + 4) * WROW;
            #pragma unroll
            for (int nt = 0; nt < 7; ++nt) {
                const int cn = (n0w + nt * 8 + gid) ^ sw;
                uint32_t bf[2] = {wrow0[cn], wrow1[cn]};
                mma16(acc[0][nt], af[0], bf);
                mma16(acc[1][nt], af[1], bf);
            }
        }
        __syncthreads();
    }

    // ---- epilogue: bias add, write k_s[slot = nq*49+kk][px] ----
    {
        const int px0 = m0w + gid;
        #pragma unroll
        for (int nt = 0; nt < 7; ++nt) {
            const int kk = nt * 8 + la * 2;
            if (kk < KK) {
                const float bias = bk[(gqp * 2 + nq) * KK + kk];
                const int s = nq * KK + kk;
                k_s[s * KROW + px0]      = acc[0][nt][0] + bias;
                k_s[s * KROW + px0 + 8]  = acc[0][nt][2] + bias;
                k_s[s * KROW + px0 + 16] = acc[1][nt][0] + bias;
                k_s[s * KROW + px0 + 24] = acc[1][nt][2] + bias;
            }
            if (kk + 1 < KK) {
                const float bias1 = bk[(gqp * 2 + nq) * KK + kk + 1];
                const int s1 = nq * KK + kk + 1;
                k_s[s1 * KROW + px0]      = acc[0][nt][1] + bias1;
                k_s[s1 * KROW + px0 + 8]  = acc[0][nt][3] + bias1;
                k_s[s1 * KROW + px0 + 16] = acc[1][nt][1] + bias1;
                k_s[s1 * KROW + px0 + 24] = acc[1][nt][3] + bias1;
            }
        }
    }
    __syncthreads();

    // ---- Stage 2: per-pixel 7x7 kernels; x from g_xh (2 channels per half2) ----
    const int pxg  = t & 15, w0 = pxg << 2;
    const int chq  = (t >> 4) & 3;
    const int grp2 = (t >> 6) & 1;
    const int hrow = t >> 7;
    const int hout = h + hrow;
    const int grpG = gqp * 2 + grp2;

    float o[2][2][4];
    #pragma unroll
    for (int mp = 0; mp < 2; ++mp)
        #pragma unroll
        for (int cc2 = 0; cc2 < 2; ++cc2)
            #pragma unroll
            for (int pi = 0; pi < 4; ++pi) o[mp][cc2][pi] = 0.0f;

    #pragma unroll
    for (int kh = 0; kh < KT; ++kh) {
        const int hh = hout + kh - 3;
        if ((unsigned)hh >= (unsigned)HH) continue;

        float4 kvf[KT];
        #pragma unroll
        for (int kw = 0; kw < KT; ++kw)
            kvf[kw] = *(const float4*)&k_s[(grp2 * KK + kh * KT + kw) * KROW + hrow * 64 + w0];

        #pragma unroll
        for (int mp = 0; mp < 2; ++mp) {
            const int cp = grpG * 8 + chq + mp * 4;
            const uint32_t* xr = g_xh + ((size_t)(b * 128 + cp)) * 4096 + hh * 64;
            uint4 A  = make_uint4(0, 0, 0, 0);
            uint4 Bv = *(const uint4*)(xr + w0);
            uint4 Cc = make_uint4(0, 0, 0, 0);
            if (pxg >= 1)  A  = *(const uint4*)(xr + w0 - 4);
            if (pxg <= 14) Cc = *(const uint4*)(xr + w0 + 4);
            float2 xv[10];
            xv[0] = u2f2(A.y);  xv[1] = u2f2(A.z);  xv[2] = u2f2(A.w);
            xv[3] = u2f2(Bv.x); xv[4] = u2f2(Bv.y); xv[5] = u2f2(Bv.z); xv[6] = u2f2(Bv.w);
            xv[7] = u2f2(Cc.x); xv[8] = u2f2(Cc.y); xv[9] = u2f2(Cc.z);
            #pragma unroll
            for (int kw = 0; kw < KT; ++kw) {
                const float kv0 = kvf[kw].x, kv1 = kvf[kw].y;
                const float kv2 = kvf[kw].z, kv3 = kvf[kw].w;
                o[mp][0][0] += xv[kw].x     * kv0;  o[mp][1][0] += xv[kw].y     * kv0;
                o[mp][0][1] += xv[kw + 1].x * kv1;  o[mp][1][1] += xv[kw + 1].y * kv1;
                o[mp][0][2] += xv[kw + 2].x * kv2;  o[mp][1][2] += xv[kw + 2].y * kv2;
                o[mp][0][3] += xv[kw + 3].x * kv3;  o[mp][1][3] += xv[kw + 3].y * kv3;
            }
        }
    }

    #pragma unroll
    for (int mp = 0; mp < 2; ++mp) {
        const int cp = grpG * 8 + chq + mp * 4;
        #pragma unroll
        for (int cc2 = 0; cc2 < 2; ++cc2) {
            const int c = 2 * cp + cc2;
            *reinterpret_cast<float4*>(out + ((size_t)(b * CH + c) * HH + hout) * WW + w0) =
                make_float4(o[mp][cc2][0], o[mp][cc2][1], o[mp][cc2][2], o[mp][cc2][3]);
        }
    }
}

extern "C" void kernel_launch(void* const* d_in, const int* in_sizes, int n_in,
                              void* d_out, int out_size) {
    const float* x  = (const float*)d_in[0];
    const float* wk = (const float*)d_in[1];
    const float* bk = (const float*)d_in[2];
    float* out      = (float*)d_out;

    x_pack_kernel<<<1024, 256>>>(x);
    wt_pack_kernel<<<512, 256>>>(wk);

    cudaFuncSetAttribute(invo_main_kernel,
                         cudaFuncAttributeMaxDynamicSharedMemorySize, SMEM_BYTES);
    dim3 grid(4 * 32, 8);               // (b*hpair, gq-pair) = (128, 8) = 1024 blocks
    invo_main_kernel<<<grid, 256, SMEM_BYTES>>>(bk, out);
}

// round 17
// speedup vs baseline: 2.1993x; 1.0409x over previous
#include <cuda_runtime.h>
#include <cuda_fp16.h>
#include <cstdint>

// Involution2d on GB300 (sm_103 base ISA). B=4, C=256, H=W=64, G=16, K=7, PAD=3.
// R17 = R16 + paired-B repack (LDS.64 B fragments) + merged pack kernel.

#define CH 256
#define HH 64
#define WW 64
#define KT 7
#define KK 49
#define CC 64                  // channels per chunk (= 32 channel-pairs)
#define NCHUNK 4
#define PX 128                 // pixels per block (2 rows)
#define KROW 132               // k_s row stride, 132%32=4 -> conflict-free

#define XBUF_U 4096            // 32 kp * 128 px  (uint32 = half2)
#define WBUF_U 4096            // 16 rr * 128 n * 2 (uint32)
#define SMEM_BYTES (2 * (XBUF_U + WBUF_U) * 4)   // 65536; k_s alias 51744 fits

// packed inputs
__device__ uint32_t g_xh[4 * 128 * 4096];   // [b][cpair][px] half2 = (x[2cp], x[2cp+1])
// paired w: [gqp][rr = chunk*16 + ks*4 + la][slot 128][2]
//   slot = nlog + 4*la  (additive de-conflict, no wrap: nlog<=111, +12<128)
//   uint2 = { h2(w[2kp],w[2kp+1]), h2(w[2kp+8],w[2kp+9]) }, kp = chunk*32+ks*8+la
__device__ uint2 g_wp2[8 * 64 * 128];

// ---------------- helpers ----------------
__device__ __forceinline__ uint32_t h2u(__half2 h) {
    uint32_t u;
    memcpy(&u, &h, 4);
    return u;
}
__device__ __forceinline__ float2 u2f2(uint32_t u) {
    __half2 h;
    memcpy(&h, &u, 4);
    return __half22float2(h);
}
__device__ __forceinline__ void cp16(void* dst, const void* src) {
    unsigned sa = (unsigned)__cvta_generic_to_shared(dst);
    asm volatile("cp.async.cg.shared.global [%0], [%1], 16;" :: "r"(sa), "l"(src));
}
__device__ __forceinline__ void cp_commit() { asm volatile("cp.async.commit_group;"); }
__device__ __forceinline__ void cp_wait1()  { asm volatile("cp.async.wait_group 1;"); }
__device__ __forceinline__ void cp_wait0()  { asm volatile("cp.async.wait_group 0;"); }

__device__ __forceinline__ void mma16(float* c, const uint32_t* a, const uint32_t* b) {
    asm volatile(
        "mma.sync.aligned.m16n8k16.row.col.f32.f16.f16.f32 "
        "{%0,%1,%2,%3}, {%4,%5,%6,%7}, {%8,%9}, {%0,%1,%2,%3};"
        : "+f"(c[0]), "+f"(c[1]), "+f"(c[2]), "+f"(c[3])
        : "r"(a[0]), "r"(a[1]), "r"(a[2]), "r"(a[3]), "r"(b[0]), "r"(b[1]));
}

// ---------------- merged pack kernel ----------------
// blocks [0,1024): x pack (2 uint4 units per thread)
// blocks [1024,1280): w pack (1 uint2 slot per thread)
__global__ __launch_bounds__(256)
void pack_kernel(const float* __restrict__ x, const float* __restrict__ wk) {
    if (blockIdx.x < 1024) {
        const int base = blockIdx.x * 512 + threadIdx.x;
        #pragma unroll
        for (int j = 0; j < 2; ++j) {
            const int u = base + j * 256;                 // 0..524287
            const int px4 = (u & 1023) << 2;
            const int cp  = (u >> 10) & 127;
            const int b   = u >> 17;
            const float4 a0 = *(const float4*)(x + ((size_t)(b * CH + 2 * cp)) * 4096 + px4);
            const float4 a1 = *(const float4*)(x + ((size_t)(b * CH + 2 * cp + 1)) * 4096 + px4);
            uint32_t o[4];
            o[0] = h2u(__floats2half2_rn(a0.x, a1.x));
            o[1] = h2u(__floats2half2_rn(a0.y, a1.y));
            o[2] = h2u(__floats2half2_rn(a0.z, a1.z));
            o[3] = h2u(__floats2half2_rn(a0.w, a1.w));
            *(uint4*)(g_xh + ((size_t)(b * 128 + cp)) * 4096 + px4) =
                make_uint4(o[0], o[1], o[2], o[3]);
        }
    } else {
        const int u = (blockIdx.x - 1024) * 256 + threadIdx.x;   // 0..65535
        const int slot = u & 127;
        const int rr   = (u >> 7) & 63;
        const int gqp  = u >> 13;
        const int la = rr & 3, ks = (rr >> 2) & 3, chunk = rr >> 4;
        const int kp = chunk * 32 + ks * 8 + la;
        const int nlog = slot - 4 * la;
        uint2 v = make_uint2(0u, 0u);
        if (nlog >= 0 && nlog < 112) {
            const int grp = nlog / 56, kk = nlog - grp * 56;
            if (kk < KK) {
                const float* src = wk + (size_t)((gqp * 2 + grp) * KK + kk) * CH;
                v.x = h2u(__floats2half2_rn(src[2 * kp],     src[2 * kp + 1]));
                v.y = h2u(__floats2half2_rn(src[2 * kp + 8], src[2 * kp + 9]));
            }
        }
        g_wp2[u] = v;
    }
}

// ---------------- fused main kernel ----------------
__global__ __launch_bounds__(256, 2)
void invo_main_kernel(const float* __restrict__ bk,
                      float* __restrict__ out) {
    extern __shared__ float sm[];
    uint32_t* smu = (uint32_t*)sm;
    float* k_s = sm;                        // [slot 98][KROW], aliased after stage 1

    const int t   = threadIdx.x;
    const int rb  = blockIdx.x;
    const int b   = rb >> 5;
    const int h   = (rb & 31) * 2;          // rows h, h+1
    const int gqp = blockIdx.y;

    auto xbuf = [&](int p) { return smu + p * XBUF_U; };
    auto wbuf = [&](int p) { return smu + 2 * XBUF_U + p * WBUF_U; };

    auto load_chunk = [&](int chunk, int pb) {
        uint32_t* xb = xbuf(pb);
        uint32_t* wb = wbuf(pb);
        #pragma unroll
        for (int i = 0; i < 4; ++i) {                 // 1024 cp16
            const int u = t + 256 * i;
            const int kp = u >> 5;                    // 0..31
            const int p4 = (u & 31) << 2;
            cp16(xb + kp * 128 + (p4 ^ (8 * (kp & 3))),
                 g_xh + ((size_t)(b * 128 + chunk * 32 + kp)) * 4096 + h * 64 + p4);
        }
        const uint32_t* wsrc = (const uint32_t*)(g_wp2 + ((size_t)(gqp * 4 + chunk)) * 16 * 128);
        #pragma unroll
        for (int i = 0; i < 4; ++i) {                 // 1024 cp16, linear
            const int u = t + 256 * i;
            cp16(wb + u * 4, wsrc + u * 4);
        }
        cp_commit();
    };

    // ---- Stage 1: mma.sync fp16, 8 warps, warp tile m32 x n56 ----
    const int wid = t >> 5, lane = t & 31;
    const int la = lane & 3, gid = lane >> 2;
    const int mq = wid & 3, nq = wid >> 2;
    const int m0w = mq * 32;
    const int n0w = nq * 56;
    const int sw = 8 * la;

    float acc[2][7][4];
    #pragma unroll
    for (int mt = 0; mt < 2; ++mt)
        #pragma unroll
        for (int nt = 0; nt < 7; ++nt)
            #pragma unroll
            for (int i = 0; i < 4; ++i) acc[mt][nt][i] = 0.0f;

    load_chunk(0, 0);
    for (int ch = 0; ch < NCHUNK; ++ch) {
        const int pb = ch & 1;
        if (ch + 1 < NCHUNK) { load_chunk(ch + 1, pb ^ 1); cp_wait1(); }
        else                 { cp_wait0(); }
        __syncthreads();

        const uint32_t* xb = xbuf(pb);
        const uint2* wb2 = (const uint2*)wbuf(pb);

        #pragma unroll
        for (int ks = 0; ks < 4; ++ks) {              // 4 x K=16 per chunk
            const int kbp = ks * 8;
            uint32_t af[2][4];
            #pragma unroll
            for (int mt = 0; mt < 2; ++mt) {
                const int rm = m0w + mt * 16;
                const int r0 = (rm + gid) ^ sw;
                const int r1 = (rm + 8 + gid) ^ sw;
                af[mt][0] = xb[(kbp + la) * 128 + r0];
                af[mt][1] = xb[(kbp + la) * 128 + r1];
                af[mt][2] = xb[(kbp + la + 4) * 128 + r0];
                af[mt][3] = xb[(kbp + la + 4) * 128 + r1];
            }
            const uint2* wrow = wb2 + (ks * 4 + la) * 128 + 4 * la;
            #pragma unroll
            for (int nt = 0; nt < 7; ++nt) {
                const uint2 bv = wrow[n0w + nt * 8 + gid];
                uint32_t bf[2] = {bv.x, bv.y};
                mma16(acc[0][nt], af[0], bf);
                mma16(acc[1][nt], af[1], bf);
            }
        }
        __syncthreads();
    }

    // ---- epilogue: bias add, write k_s[slot = nq*49+kk][px] ----
    {
        const int px0 = m0w + gid;
        #pragma unroll
        for (int nt = 0; nt < 7; ++nt) {
            const int kk = nt * 8 + la * 2;
            if (kk < KK) {
                const float bias = bk[(gqp * 2 + nq) * KK + kk];
                const int s = nq * KK + kk;
                k_s[s * KROW + px0]      = acc[0][nt][0] + bias;
                k_s[s * KROW + px0 + 8]  = acc[0][nt][2] + bias;
                k_s[s * KROW + px0 + 16] = acc[1][nt][0] + bias;
                k_s[s * KROW + px0 + 24] = acc[1][nt][2] + bias;
            }
            if (kk + 1 < KK) {
                const float bias1 = bk[(gqp * 2 + nq) * KK + kk + 1];
                const int s1 = nq * KK + kk + 1;
                k_s[s1 * KROW + px0]      = acc[0][nt][1] + bias1;
                k_s[s1 * KROW + px0 + 8]  = acc[0][nt][3] + bias1;
                k_s[s1 * KROW + px0 + 16] = acc[1][nt][1] + bias1;
                k_s[s1 * KROW + px0 + 24] = acc[1][nt][3] + bias1;
            }
        }
    }
    __syncthreads();

    // ---- Stage 2: per-pixel 7x7 kernels; x from g_xh (2 channels per half2) ----
    const int pxg  = t & 15, w0 = pxg << 2;
    const int chq  = (t >> 4) & 3;
    const int grp2 = (t >> 6) & 1;
    const int hrow = t >> 7;
    const int hout = h + hrow;
    const int grpG = gqp * 2 + grp2;

    float o[2][2][4];
    #pragma unroll
    for (int mp = 0; mp < 2; ++mp)
        #pragma unroll
        for (int cc2 = 0; cc2 < 2; ++cc2)
            #pragma unroll
            for (int pi = 0; pi < 4; ++pi) o[mp][cc2][pi] = 0.0f;

    #pragma unroll
    for (int kh = 0; kh < KT; ++kh) {
        const int hh = hout + kh - 3;
        if ((unsigned)hh >= (unsigned)HH) continue;

        float4 kvf[KT];
        #pragma unroll
        for (int kw = 0; kw < KT; ++kw)
            kvf[kw] = *(const float4*)&k_s[(grp2 * KK + kh * KT + kw) * KROW + hrow * 64 + w0];

        #pragma unroll
        for (int mp = 0; mp < 2; ++mp) {
            const int cp = grpG * 8 + chq + mp * 4;
            const uint32_t* xr = g_xh + ((size_t)(b * 128 + cp)) * 4096 + hh * 64;
            uint4 A  = make_uint4(0, 0, 0, 0);
            uint4 Bv = *(const uint4*)(xr + w0);
            uint4 Cc = make_uint4(0, 0, 0, 0);
            if (pxg >= 1)  A  = *(const uint4*)(xr + w0 - 4);
            if (pxg <= 14) Cc = *(const uint4*)(xr + w0 + 4);
            float2 xv[10];
            xv[0] = u2f2(A.y);  xv[1] = u2f2(A.z);  xv[2] = u2f2(A.w);
            xv[3] = u2f2(Bv.x); xv[4] = u2f2(Bv.y); xv[5] = u2f2(Bv.z); xv[6] = u2f2(Bv.w);
            xv[7] = u2f2(Cc.x); xv[8] = u2f2(Cc.y); xv[9] = u2f2(Cc.z);
            #pragma unroll
            for (int kw = 0; kw < KT; ++kw) {
                const float kv0 = kvf[kw].x, kv1 = kvf[kw].y;
                const float kv2 = kvf[kw].z, kv3 = kvf[kw].w;
                o[mp][0][0] += xv[kw].x     * kv0;  o[mp][1][0] += xv[kw].y     * kv0;
                o[mp][0][1] += xv[kw + 1].x * kv1;  o[mp][1][1] += xv[kw + 1].y * kv1;
                o[mp][0][2] += xv[kw + 2].x * kv2;  o[mp][1][2] += xv[kw + 2].y * kv2;
                o[mp][0][3] += xv[kw + 3].x * kv3;  o[mp][1][3] += xv[kw + 3].y * kv3;
            }
        }
    }

    #pragma unroll
    for (int mp = 0; mp < 2; ++mp) {
        const int cp = grpG * 8 + chq + mp * 4;
        #pragma unroll
        for (int cc2 = 0; cc2 < 2; ++cc2) {
            const int c = 2 * cp + cc2;
            *reinterpret_cast<float4*>(out + ((size_t)(b * CH + c) * HH + hout) * WW + w0) =
                make_float4(o[mp][cc2][0], o[mp][cc2][1], o[mp][cc2][2], o[mp][cc2][3]);
        }
    }
}

extern "C" void kernel_launch(void* const* d_in, const int* in_sizes, int n_in,
                              void* d_out, int out_size) {
    const float* x  = (const float*)d_in[0];
    const float* wk = (const float*)d_in[1];
    const float* bk = (const float*)d_in[2];
    float* out      = (float*)d_out;

    pack_kernel<<<1280, 256>>>(x, wk);

    cudaFuncSetAttribute(invo_main_kernel,
                         cudaFuncAttributeMaxDynamicSharedMemorySize, SMEM_BYTES);
    dim3 grid(4 * 32, 8);               // (b*hpair, gq-pair) = (128, 8) = 1024 blocks
    invo_main_kernel<<<grid, 256, SMEM_BYTES>>>(bk, out);
}